// round 9
// baseline (speedup 1.0000x reference)
#include <cuda_runtime.h>
#include <math_constants.h>

// SoftmaxTreeWithLoss on GB300 (sm_103a).
// x: [N=16, C=4096, H=26, W=26] f32; label: [N,26,26] i32 in [0,C)
// Tree: group 0 = channels [0,512) (roots); then 512 groups of 7 children.
//
// loss_pos = -( child-group logps + x[root_node] - LSE(root group) )
// and for this tree every position hits group 0 exactly once (root_cnt == 1),
// but we compute root_cnt explicitly to stay faithful to the reference.
//
// R8: transpose the streaming decomposition. CTA = (n, 32-channel block);
// each warp streams 4 CONTIGUOUS channel rows sequentially (11 independent
// 256B loads issued before any __expf) -> DRAM row-buffer friendly + MLP~11
// with 2048 streaming warps. Per-position partial exp-sums go through smem,
// then one spread atomicAdd pass into __device__ g_S[pos]. Chain blocks
// (S-independent part) overlap in the same kernel. Kernel 2 adds
// root_cnt[pos]*log(g_S[pos]).

#define HW_SZ 676              // 26*26
#define HF2   338              // HW_SZ/2 (float2 per channel row)
#define CN 4096
#define NCB 16                 // 512 root channels / 32 per CTA
#define CH_PER_WARP 4
#define THREADS 256

__device__ float g_S[16 * HW_SZ];      // per-position exp-sum (zeroed per launch)
__device__ float g_rcnt[16 * HW_SZ];   // per-position root-group visit count

// ---------------- kernel 1: streaming partial exp-sums + chain walk ----------------
__global__ __launch_bounds__(THREADS, 3)
void k1_stream_chain(const float* __restrict__ x,
                     const int*   __restrict__ label,
                     const int*   __restrict__ group_offsets,
                     const int*   __restrict__ group_sizes,
                     const int*   __restrict__ cid_groups,
                     const int*   __restrict__ parents,
                     float* __restrict__ out,
                     int M, int nStreamBlocks, float inv_norm)
{
    __shared__ float2 sm[8][HF2];      // per-warp per-position partials
    __shared__ float  red[8];

    const int lane = threadIdx.x & 31;
    const int w    = threadIdx.x >> 5;

    if ((int)blockIdx.x < nStreamBlocks) {
        // ================= streaming CTA: (n, 32-channel block) =================
        const int n  = blockIdx.x >> 4;          // image
        const int cb = blockIdx.x & 15;          // channel block
        const int c0 = cb * 32 + w * CH_PER_WARP;
        const float2* p = (const float2*)x + ((size_t)n * CN + c0) * HF2;

        float2 acc[11];
        #pragma unroll
        for (int i = 0; i < 11; i++) acc[i] = make_float2(0.f, 0.f);

        #pragma unroll
        for (int ch = 0; ch < CH_PER_WARP; ch++) {
            const float2* cp = p + ch * HF2;
            float2 b[11];
            // 11 independent 256B warp-loads, all issued before consumption
            #pragma unroll
            for (int i = 0; i < 10; i++) b[i] = cp[lane + 32 * i];
            b[10] = cp[320 + lane];              // may overread into next row: safe, masked below
            #pragma unroll
            for (int i = 0; i < 10; i++) {
                acc[i].x += __expf(b[i].x);
                acc[i].y += __expf(b[i].y);
            }
            if (lane < HF2 - 320) {              // 338-320 = 18 valid tail lanes
                acc[10].x += __expf(b[10].x);
                acc[10].y += __expf(b[10].y);
            }
        }

        // stash this warp's per-position partials
        #pragma unroll
        for (int i = 0; i < 10; i++) sm[w][lane + 32 * i] = acc[i];
        if (lane < HF2 - 320) sm[w][320 + lane] = acc[10];
        __syncthreads();

        // merge 8 warps, one spread atomicAdd per position into g_S
        float* gs = g_S + n * HW_SZ;
        for (int e = threadIdx.x; e < HF2; e += THREADS) {
            float sx = 0.f, sy = 0.f;
            #pragma unroll
            for (int q = 0; q < 8; q++) { sx += sm[q][e].x; sy += sm[q][e].y; }
            atomicAdd(&gs[2 * e],     sx);
            atomicAdd(&gs[2 * e + 1], sy);
        }
    } else {
        // ================= chain CTA: S-independent part of the loss =================
        const int pos = ((int)blockIdx.x - nStreamBlocks) * THREADS + threadIdx.x;
        const bool valid = pos < M;
        const int n  = valid ? (pos / HW_SZ) : 0;
        const int hw = valid ? (pos - n * HW_SZ) : 0;
        const float* base = x + (size_t)n * (CN * HW_SZ) + hw;

        float child_lp   = 0.f;
        float root_logit = 0.f;
        float root_cnt   = 0.f;

        int cur = valid ? label[pos] : -1;
        #pragma unroll 1
        for (int d = 0; d < 8; d++) {            // MAX_DEPTH = 8
            if (!__ballot_sync(0xffffffffu, cur >= 0)) break;
            if (cur >= 0) {
                const int g = cid_groups[cur];
                if (g == 0) {
                    root_logit += base[cur * HW_SZ];
                    root_cnt   += 1.f;
                } else {
                    const int go = group_offsets[g];
                    const int gs = group_sizes[g];   // 7
                    float ss = 0.f, xv = 0.f;
                    for (int j = 0; j < gs; j++) {
                        const float v = base[(go + j) * HW_SZ];
                        ss += __expf(v);
                        if (go + j == cur) xv = v;
                    }
                    child_lp += xv - __logf(ss);
                }
                cur = parents[cur];
            }
        }

        if (valid) g_rcnt[pos] = root_cnt;

        // block-reduce -(child_lp + root_logit), one atomic per block
        float v = valid ? -(child_lp + root_logit) : 0.f;
        #pragma unroll
        for (int o = 16; o; o >>= 1) v += __shfl_xor_sync(0xffffffffu, v, o);
        if (lane == 0) red[w] = v;
        __syncthreads();
        if (w == 0) {
            float t = (lane < 8) ? red[lane] : 0.f;
            #pragma unroll
            for (int o = 4; o; o >>= 1) t += __shfl_xor_sync(0xffffffffu, t, o);
            if (lane == 0) atomicAdd(out, t * inv_norm);
        }
    }
}

// ---------------- kernel 2: add root_cnt[pos] * log(S[pos]) ----------------
__global__ __launch_bounds__(THREADS, 4)
void k2_finish(float* __restrict__ out, int M, float inv_norm)
{
    __shared__ float red[8];
    const int lane = threadIdx.x & 31;
    const int w    = threadIdx.x >> 5;
    const int pos  = blockIdx.x * THREADS + threadIdx.x;

    float v = 0.f;
    if (pos < M)
        v = g_rcnt[pos] * __logf(g_S[pos]);

    #pragma unroll
    for (int o = 16; o; o >>= 1) v += __shfl_xor_sync(0xffffffffu, v, o);
    if (lane == 0) red[w] = v;
    __syncthreads();
    if (w == 0) {
        float t = (lane < 8) ? red[lane] : 0.f;
        #pragma unroll
        for (int o = 4; o; o >>= 1) t += __shfl_xor_sync(0xffffffffu, t, o);
        if (lane == 0) atomicAdd(out, t * inv_norm);
    }
}

extern "C" void kernel_launch(void* const* d_in, const int* in_sizes, int n_in,
                              void* d_out, int out_size)
{
    const float* x     = (const float*)d_in[0];
    const int* label   = (const int*)d_in[1];
    const int* g_off   = (const int*)d_in[2];
    const int* g_sz    = (const int*)d_in[3];
    const int* cid     = (const int*)d_in[4];
    const int* par     = (const int*)d_in[5];
    float* out         = (float*)d_out;

    const int M = in_sizes[1];            // N*H*W
    const int N = M / HW_SZ;              // batch size
    const float inv_norm = 1.0f / (float)N;

    void* gS_addr = nullptr;
    cudaGetSymbolAddress(&gS_addr, g_S);
    cudaMemsetAsync(gS_addr, 0, (size_t)M * sizeof(float));
    cudaMemsetAsync(d_out, 0, sizeof(float));

    const int nStreamBlocks = N * NCB;                      // 256
    const int chainBlocks   = (M + THREADS - 1) / THREADS;  // 43
    k1_stream_chain<<<nStreamBlocks + chainBlocks, THREADS>>>(
        x, label, g_off, g_sz, cid, par, out, M, nStreamBlocks, inv_norm);
    k2_finish<<<chainBlocks, THREADS>>>(out, M, inv_norm);
}

// round 10
// speedup vs baseline: 1.3083x; 1.3083x over previous
#include <cuda_runtime.h>
#include <math_constants.h>
#include <cstdint>

// SoftmaxTreeWithLoss on GB300 (sm_103a).
// x: [N=16, C=4096, H=26, W=26] f32; label: [N,26,26] i32 in [0,C)
// Tree: group 0 = channels [0,512) (roots); then 512 groups of 7 children.
// loss_pos = -( child-group logps + x[root] - LSE(root group) ).
//
// R9: R6's warp-specialized skeleton (8 streaming warps + 1 chain warp per
// 32-position CTA), but streaming via cp.async (LDGSTS) into smem: load issue
// is fire-and-forget (no dest register, no ptxas scheduling dependence), so
// each warp keeps up to 8KB (64 x 128B channel rows) in flight. Consumption
// (LDS + __expf) drains behind wait_group pipelining.

#define HW_SZ 676              // 26*26
#define CN 4096
#define POS_PER_BLOCK 32
#define NW_STREAM 8
#define CH_PER_WARP 64         // 512 / 8
#define THREADS 288            // 8 stream + 1 chain warp
#define WARP_SMEM (CH_PER_WARP * POS_PER_BLOCK * 4)   // 8192 B per warp
#define DSMEM_BYTES (NW_STREAM * WARP_SMEM)           // 65536 B

__device__ __forceinline__ void cp_async16(uint32_t dst, const void* src) {
    asm volatile("cp.async.ca.shared.global [%0], [%1], 16;"
                 :: "r"(dst), "l"(src) : "memory");
}
__device__ __forceinline__ void cp_commit() {
    asm volatile("cp.async.commit_group;" ::: "memory");
}
template <int N>
__device__ __forceinline__ void cp_wait() {
    asm volatile("cp.async.wait_group %0;" :: "n"(N) : "memory");
}

__global__ __launch_bounds__(THREADS, 3)
void tree_loss_kernel(const float* __restrict__ x,
                      const int*   __restrict__ label,
                      const int*   __restrict__ group_offsets,
                      const int*   __restrict__ group_sizes,
                      const int*   __restrict__ cid_groups,
                      const int*   __restrict__ parents,
                      float* __restrict__ out,
                      int M, float inv_norm)
{
    extern __shared__ char dsm[];                 // 64KB: stream tiles
    __shared__ float sm_s[NW_STREAM][POS_PER_BLOCK];

    const int lane = threadIdx.x & 31;
    const int w    = threadIdx.x >> 5;

    if (w < NW_STREAM) {
        // ============ streaming warp: 64 channels x 32 positions ============
        // cp.async instr i: channels c0 + 4i + (lane>>3), positions
        // blk*32 + (lane&7)*4 .. +3  (16B per lane, 512B per warp-instr).
        // 676 % 4 == 0 => a 4-position run never straddles an image boundary.
        const int c0  = w * CH_PER_WARP;
        const int q4  = (lane & 7) * 4;                 // position offset
        const int chh = lane >> 3;                      // 0..3
        int P = blockIdx.x * POS_PER_BLOCK + q4;
        if (P >= M) P = 0;                              // safe dummy (masked later)
        const int n  = P / HW_SZ;
        const int hw = P - n * HW_SZ;

        const float* src = x + ((size_t)n * CN + c0 + chh) * HW_SZ + hw;
        uint32_t dst = (uint32_t)__cvta_generic_to_shared(dsm)
                     + w * WARP_SMEM + chh * 128 + (lane & 7) * 16;

        // issue all 64 channel rows as 4 commit-groups of 16 channels
        #pragma unroll
        for (int g = 0; g < 4; g++) {
            #pragma unroll
            for (int i = 0; i < 4; i++) {
                cp_async16(dst, src);
                dst += 512;                 // 4 channels * 128B
                src += 4 * HW_SZ;
            }
            cp_commit();
        }

        // drain + consume: thread lane owns position `lane`
        const float* wb = (const float*)(dsm + w * WARP_SMEM);
        float a0 = 0.f, a1 = 0.f, a2 = 0.f, a3 = 0.f;

        cp_wait<3>(); __syncwarp();
        #pragma unroll
        for (int c = 0; c < 16; c += 4) {
            a0 += __expf(wb[(c + 0) * 32 + lane]);
            a1 += __expf(wb[(c + 1) * 32 + lane]);
            a2 += __expf(wb[(c + 2) * 32 + lane]);
            a3 += __expf(wb[(c + 3) * 32 + lane]);
        }
        cp_wait<2>(); __syncwarp();
        #pragma unroll
        for (int c = 16; c < 32; c += 4) {
            a0 += __expf(wb[(c + 0) * 32 + lane]);
            a1 += __expf(wb[(c + 1) * 32 + lane]);
            a2 += __expf(wb[(c + 2) * 32 + lane]);
            a3 += __expf(wb[(c + 3) * 32 + lane]);
        }
        cp_wait<1>(); __syncwarp();
        #pragma unroll
        for (int c = 32; c < 48; c += 4) {
            a0 += __expf(wb[(c + 0) * 32 + lane]);
            a1 += __expf(wb[(c + 1) * 32 + lane]);
            a2 += __expf(wb[(c + 2) * 32 + lane]);
            a3 += __expf(wb[(c + 3) * 32 + lane]);
        }
        cp_wait<0>(); __syncwarp();
        #pragma unroll
        for (int c = 48; c < 64; c += 4) {
            a0 += __expf(wb[(c + 0) * 32 + lane]);
            a1 += __expf(wb[(c + 1) * 32 + lane]);
            a2 += __expf(wb[(c + 2) * 32 + lane]);
            a3 += __expf(wb[(c + 3) * 32 + lane]);
        }

        sm_s[w][lane] = (a0 + a1) + (a2 + a3);
        __syncthreads();
    } else {
        // ============ chain warp: parent-chain walk, overlapped ============
        const int pos = blockIdx.x * POS_PER_BLOCK + lane;
        const bool valid = pos < M;
        const int n  = valid ? (pos / HW_SZ) : 0;
        const int hw = valid ? (pos - n * HW_SZ) : 0;
        const float* base = x + (size_t)n * (CN * HW_SZ) + hw;

        float child_lp   = 0.f;   // self-contained child-group log-probs
        float root_logit = 0.f;   // group-0 logits on the chain
        float root_cnt   = 0.f;   // # group-0 terms (each needs lse0)

        int cur = valid ? label[pos] : -1;
        #pragma unroll 1
        for (int d = 0; d < 8; d++) {            // MAX_DEPTH = 8
            if (!__ballot_sync(0xffffffffu, cur >= 0)) break;
            if (cur >= 0) {
                const int g = cid_groups[cur];
                if (g == 0) {
                    root_logit += base[cur * HW_SZ];
                    root_cnt   += 1.f;
                } else {
                    const int go = group_offsets[g];
                    const int gs = group_sizes[g];   // 7
                    float ss = 0.f, xv = 0.f;
                    for (int j = 0; j < gs; j++) {
                        const float v = base[(go + j) * HW_SZ];
                        ss += __expf(v);
                        if (go + j == cur) xv = v;
                    }
                    child_lp += xv - __logf(ss);
                }
                cur = parents[cur];
            }
        }

        __syncthreads();

        // merge the 8 streaming partials for this position
        float S = 0.f;
        #pragma unroll
        for (int q = 0; q < NW_STREAM; q++) S += sm_s[q][lane];

        float loss = 0.f;
        if (valid)
            loss = -(child_lp + root_logit - root_cnt * __logf(S));

        #pragma unroll
        for (int o = 16; o; o >>= 1)
            loss += __shfl_xor_sync(0xffffffffu, loss, o);
        if (lane == 0)
            atomicAdd(out, loss * inv_norm);
    }
}

extern "C" void kernel_launch(void* const* d_in, const int* in_sizes, int n_in,
                              void* d_out, int out_size)
{
    const float* x     = (const float*)d_in[0];
    const int* label   = (const int*)d_in[1];
    const int* g_off   = (const int*)d_in[2];
    const int* g_sz    = (const int*)d_in[3];
    const int* cid     = (const int*)d_in[4];
    const int* par     = (const int*)d_in[5];
    float* out         = (float*)d_out;

    const int M = in_sizes[1];          // N*H*W (label element count)
    const int N = M / HW_SZ;            // batch size for normalization
    const float inv_norm = 1.0f / (float)N;

    static bool attr_done = false;
    if (!attr_done) {
        cudaFuncSetAttribute(tree_loss_kernel,
                             cudaFuncAttributeMaxDynamicSharedMemorySize,
                             DSMEM_BYTES);
        attr_done = true;
    }

    cudaMemsetAsync(d_out, 0, sizeof(float));

    const int blocks = (M + POS_PER_BLOCK - 1) / POS_PER_BLOCK;
    tree_loss_kernel<<<blocks, THREADS, DSMEM_BYTES>>>(
        x, label, g_off, g_sz, cid, par, out, M, inv_norm);
}